// round 1
// baseline (speedup 1.0000x reference)
#include <cuda_runtime.h>

// crossMSEloss: B=4, S=256, P=64, D=63
// inputs:  (B,S,P,D+1) f32  -> d_in[0], per (b,s): 64x64 block (last col = conf)
// targets: (B,S,P,D)   f32  -> d_in[1], per (b,s): 64x63 block
// out:     (B,S) f32 = 1024 elements
//
// out[b,s] = sum_p conf[p] * min_q ||pred_p - tgt_q||
//          + sum_q min_p ( ||pred_p - tgt_q|| / conf[p] )

#define NP 64
#define ND 63
#define STRIDE 65   // smem row stride: 65 -> bank = (row + col) % 32, conflict-free rows & cols

__global__ __launch_bounds__(256, 4)
void cross_mse_loss_kernel(const float* __restrict__ inp,
                           const float* __restrict__ tgt,
                           float* __restrict__ out)
{
    __shared__ float sp[NP * STRIDE];   // preds  [p][d]
    __shared__ float st[NP * STRIDE];   // targets[q][d]
    __shared__ float sd[NP * STRIDE];   // dist   [p][q]
    __shared__ float conf[NP];
    __shared__ float cinv[NP];
    __shared__ float red[128];

    const int bs  = blockIdx.x;
    const int tid = threadIdx.x;

    const float* ip = inp + (size_t)bs * (NP * 64);   // 64x64 contiguous
    const float* tp = tgt + (size_t)bs * (NP * ND);   // 64x63 contiguous

    // Load inputs: 4096 floats; column 63 is confidence
    #pragma unroll 4
    for (int i = tid; i < NP * 64; i += 256) {
        float v = ip[i];
        int p = i >> 6;
        int d = i & 63;
        if (d == ND) {
            conf[p] = v;
            cinv[p] = 1.0f / v;
        } else {
            sp[p * STRIDE + d] = v;
        }
    }
    // Load targets: 4032 floats
    #pragma unroll 4
    for (int i = tid; i < NP * ND; i += 256) {
        int q = i / ND;
        int d = i - q * ND;
        st[q * STRIDE + d] = tp[i];
    }
    __syncthreads();

    // 4x4 register tile per thread over the 64x64 pair matrix.
    // 16x16 thread grid: tx -> q tile, ty -> p tile.
    const int tx = tid & 15;
    const int ty = tid >> 4;
    const int p0 = ty * 4;
    const int q0 = tx * 4;

    float acc[4][4];
    #pragma unroll
    for (int i = 0; i < 4; i++)
        #pragma unroll
        for (int j = 0; j < 4; j++)
            acc[i][j] = 0.0f;

    #pragma unroll 7
    for (int d = 0; d < ND; d++) {
        float a0 = sp[(p0 + 0) * STRIDE + d];
        float a1 = sp[(p0 + 1) * STRIDE + d];
        float a2 = sp[(p0 + 2) * STRIDE + d];
        float a3 = sp[(p0 + 3) * STRIDE + d];
        float b0 = st[(q0 + 0) * STRIDE + d];
        float b1 = st[(q0 + 1) * STRIDE + d];
        float b2 = st[(q0 + 2) * STRIDE + d];
        float b3 = st[(q0 + 3) * STRIDE + d];
        float a[4] = {a0, a1, a2, a3};
        float b[4] = {b0, b1, b2, b3};
        #pragma unroll
        for (int i = 0; i < 4; i++)
            #pragma unroll
            for (int j = 0; j < 4; j++) {
                float df = a[i] - b[j];
                acc[i][j] = fmaf(df, df, acc[i][j]);
            }
    }

    // Write sqrt'd distances
    #pragma unroll
    for (int i = 0; i < 4; i++)
        #pragma unroll
        for (int j = 0; j < 4; j++)
            sd[(p0 + i) * STRIDE + (q0 + j)] = sqrtf(acc[i][j]);
    __syncthreads();

    // Reductions: threads 0..63 do row mins (term1), 64..127 do col mins (term2)
    float val = 0.0f;
    if (tid < NP) {
        const int p = tid;
        float m = sd[p * STRIDE + 0];
        #pragma unroll 8
        for (int q = 1; q < NP; q++)
            m = fminf(m, sd[p * STRIDE + q]);
        val = conf[p] * m;
    } else if (tid < 2 * NP) {
        const int q = tid - NP;
        float m = sd[0 * STRIDE + q] * cinv[0];
        #pragma unroll 8
        for (int p = 1; p < NP; p++)
            m = fminf(m, sd[p * STRIDE + q] * cinv[p]);
        val = m;
    }

    if (tid < 128) red[tid] = val;
    __syncthreads();

    if (tid < 64) red[tid] += red[tid + 64];
    __syncthreads();

    if (tid < 32) {
        float s = red[tid] + red[tid + 32];
        #pragma unroll
        for (int off = 16; off > 0; off >>= 1)
            s += __shfl_down_sync(0xFFFFFFFFu, s, off);
        if (tid == 0) out[bs] = s;
    }
}

extern "C" void kernel_launch(void* const* d_in, const int* in_sizes, int n_in,
                              void* d_out, int out_size)
{
    const float* inp = (const float*)d_in[0];
    const float* tgt = (const float*)d_in[1];
    float* out = (float*)d_out;
    // B*S = 1024 blocks
    cross_mse_loss_kernel<<<1024, 256>>>(inp, tgt, out);
}

// round 2
// speedup vs baseline: 1.5543x; 1.5543x over previous
#include <cuda_runtime.h>

// crossMSEloss: B=4, S=256, P=64, D=63
// out[b,s] = sum_p conf[p] * min_q ||pred_p - tgt_q||
//          + sum_q min_p ( ||pred_p - tgt_q|| / conf[p] )
//
// Strategy: ||p-q||^2 = ||p||^2 + ||q||^2 - 2 p.q  (GEMM-form inner loop,
// 1 FFMA/element). Mins taken on squared distances (sqrt is monotonic;
// term2 uses cinv^2), so only 128 sqrts/block. No distance matrix in smem.

#define NP 64
#define SP_S 65    // preds row stride (scalar broadcast reads; conflict-free norm reads)
#define ST_S 65    // target staging stride
#define STT_S 68   // transposed target stride: 16B-aligned float4 rows, conflict-free

__global__ __launch_bounds__(256, 4)
void cross_mse_loss_kernel(const float* __restrict__ inp,
                           const float* __restrict__ tgt,
                           float* __restrict__ out)
{
    __shared__ float sp[NP * SP_S];      // preds  [p][d], d=63 zero-padded
    __shared__ float st[NP * ST_S];      // target staging [q][d]; aliased by rm/cm later
    __shared__ float st_t[NP * STT_S];   // targets transposed [d][q]
    __shared__ float conf[NP];
    __shared__ float cinv2[NP];
    __shared__ float pn[NP];             // ||pred_p||^2
    __shared__ float qn[NP];             // ||tgt_q||^2
    __shared__ float pp[256];            // norm partials
    __shared__ float qp[256];
    __shared__ float red[128];

    // rm/cm alias the st staging buffer (st is dead after the pre-mainloop sync)
    float* rm = st;              // [16][65] row-min partials (indexed by tx)
    float* cm = st + 16 * 65;    // [16][65] col-min partials (indexed by ty)

    const int bs  = blockIdx.x;
    const int tid = threadIdx.x;

    const float* ip = inp + (size_t)bs * (NP * 64);
    const float* tp = tgt + (size_t)bs * (NP * 63);

    // ---- Load preds (+conf) via float4, zero-pad d=63 ----
    const float4* ip4 = (const float4*)ip;
    #pragma unroll
    for (int r = 0; r < 4; r++) {
        int idx = tid + r * 256;          // 1024 float4 total
        float4 v = ip4[idx];
        int p  = idx >> 4;
        int d4 = (idx & 15) << 2;
        float* row = sp + p * SP_S + d4;
        if (d4 == 60) {
            row[0] = v.x; row[1] = v.y; row[2] = v.z; row[3] = 0.0f;
            conf[p] = v.w;
            float ci = 1.0f / v.w;
            cinv2[p] = ci * ci;
        } else {
            row[0] = v.x; row[1] = v.y; row[2] = v.z; row[3] = v.w;
        }
    }
    // ---- Load targets (scalar, coalesced), zero-pad d=63 ----
    #pragma unroll
    for (int r = 0; r < 16; r++) {
        int i = tid + r * 256;
        if (i < NP * 63) {
            int q = i / 63;
            int d = i - q * 63;
            st[q * ST_S + d] = tp[i];
        }
    }
    if (tid < NP) st[tid * ST_S + 63] = 0.0f;
    __syncthreads();

    // ---- Transpose targets into st_t[d][q] (read & write conflict-free) ----
    #pragma unroll
    for (int r = 0; r < 16; r++) {
        int i = tid + r * 256;            // 4096
        int d = i >> 6;
        int q = i & 63;
        st_t[d * STT_S + q] = st[q * ST_S + d];
    }
    // ---- Norm partials: 4 groups of 16 d's per point ----
    {
        int p = tid & 63;
        int g = tid >> 6;
        const float* ap = sp + p * SP_S + g * 16;
        const float* bp = st + p * ST_S + g * 16;
        float s1 = 0.0f, s2 = 0.0f;
        #pragma unroll
        for (int k = 0; k < 16; k++) {
            float a = ap[k];
            float b = bp[k];
            s1 = fmaf(a, a, s1);
            s2 = fmaf(b, b, s2);
        }
        pp[tid] = s1;
        qp[tid] = s2;
    }
    __syncthreads();
    if (tid < NP) {
        pn[tid] = (pp[tid] + pp[tid + 64]) + (pp[tid + 128] + pp[tid + 192]);
    } else if (tid < 2 * NP) {
        int q = tid - NP;
        qn[q] = (qp[q] + qp[q + 64]) + (qp[q + 128] + qp[q + 192]);
    }
    __syncthreads();

    // ---- Main loop: dot[p][q] via 4x4 register tiles over 16x16 threads ----
    const int tx = tid & 15;
    const int ty = tid >> 4;
    const int p0 = ty * 4;
    const int q0 = tx * 4;

    float acc[4][4];
    #pragma unroll
    for (int i = 0; i < 4; i++)
        #pragma unroll
        for (int j = 0; j < 4; j++)
            acc[i][j] = 0.0f;

    const float* bbase = st_t + q0;
    #pragma unroll 2
    for (int dc = 0; dc < 64; dc += 4) {
        float4 b0 = *(const float4*)(bbase + (dc + 0) * STT_S);
        float4 b1 = *(const float4*)(bbase + (dc + 1) * STT_S);
        float4 b2 = *(const float4*)(bbase + (dc + 2) * STT_S);
        float4 b3 = *(const float4*)(bbase + (dc + 3) * STT_S);
        #pragma unroll
        for (int i = 0; i < 4; i++) {
            const float* arow = sp + (p0 + i) * SP_S + dc;
            float a0 = arow[0], a1 = arow[1], a2 = arow[2], a3 = arow[3];
            acc[i][0] = fmaf(a0, b0.x, acc[i][0]);
            acc[i][1] = fmaf(a0, b0.y, acc[i][1]);
            acc[i][2] = fmaf(a0, b0.z, acc[i][2]);
            acc[i][3] = fmaf(a0, b0.w, acc[i][3]);
            acc[i][0] = fmaf(a1, b1.x, acc[i][0]);
            acc[i][1] = fmaf(a1, b1.y, acc[i][1]);
            acc[i][2] = fmaf(a1, b1.z, acc[i][2]);
            acc[i][3] = fmaf(a1, b1.w, acc[i][3]);
            acc[i][0] = fmaf(a2, b2.x, acc[i][0]);
            acc[i][1] = fmaf(a2, b2.y, acc[i][1]);
            acc[i][2] = fmaf(a2, b2.z, acc[i][2]);
            acc[i][3] = fmaf(a2, b2.w, acc[i][3]);
            acc[i][0] = fmaf(a3, b3.x, acc[i][0]);
            acc[i][1] = fmaf(a3, b3.y, acc[i][1]);
            acc[i][2] = fmaf(a3, b3.z, acc[i][2]);
            acc[i][3] = fmaf(a3, b3.w, acc[i][3]);
        }
    }

    // ---- Per-thread epilogue: d^2, partial row/col mins (no sqrt yet) ----
    float pnr[4], ci2[4], qnr[4];
    #pragma unroll
    for (int i = 0; i < 4; i++) { pnr[i] = pn[p0 + i]; ci2[i] = cinv2[p0 + i]; }
    #pragma unroll
    for (int j = 0; j < 4; j++) qnr[j] = qn[q0 + j];

    float rmin[4] = {1e30f, 1e30f, 1e30f, 1e30f};
    float cmin[4] = {1e30f, 1e30f, 1e30f, 1e30f};
    #pragma unroll
    for (int i = 0; i < 4; i++) {
        #pragma unroll
        for (int j = 0; j < 4; j++) {
            float d2 = fmaxf(fmaf(-2.0f, acc[i][j], pnr[i] + qnr[j]), 0.0f);
            rmin[i] = fminf(rmin[i], d2);
            cmin[j] = fminf(cmin[j], d2 * ci2[i]);
        }
    }
    #pragma unroll
    for (int i = 0; i < 4; i++) rm[tx * 65 + p0 + i] = rmin[i];
    #pragma unroll
    for (int j = 0; j < 4; j++) cm[ty * 65 + q0 + j] = cmin[j];
    __syncthreads();

    // ---- Final mins + 128 sqrts + block sum ----
    float val = 0.0f;
    if (tid < NP) {
        const int p = tid;
        float m = rm[p];
        #pragma unroll
        for (int t = 1; t < 16; t++) m = fminf(m, rm[t * 65 + p]);
        val = conf[p] * sqrtf(m);
    } else if (tid < 2 * NP) {
        const int q = tid - NP;
        float m = cm[q];
        #pragma unroll
        for (int t = 1; t < 16; t++) m = fminf(m, cm[t * 65 + q]);
        val = sqrtf(m);
    }

    if (tid < 128) red[tid] = val;
    __syncthreads();
    if (tid < 64) red[tid] += red[tid + 64];
    __syncthreads();
    if (tid < 32) {
        float s = red[tid] + red[tid + 32];
        #pragma unroll
        for (int off = 16; off > 0; off >>= 1)
            s += __shfl_down_sync(0xFFFFFFFFu, s, off);
        if (tid == 0) out[bs] = s;
    }
}

extern "C" void kernel_launch(void* const* d_in, const int* in_sizes, int n_in,
                              void* d_out, int out_size)
{
    const float* inp = (const float*)d_in[0];
    const float* tgt = (const float*)d_in[1];
    float* out = (float*)d_out;
    cross_mse_loss_kernel<<<1024, 256>>>(inp, tgt, out);
}

// round 3
// speedup vs baseline: 1.5563x; 1.0013x over previous
#include <cuda_runtime.h>

// crossMSEloss: B=4, S=256, P=64, D=63
// out[b,s] = sum_p conf[p] * min_q ||pred_p - tgt_q||
//          + sum_q min_p ( ||pred_p - tgt_q|| / conf[p] )
//
// GEMM-form: ||p-q||^2 = ||p||^2+||q||^2-2 p.q; mins on squared distances.
// Mainloop uses Blackwell packed fp32 FMA (fma.rn.f32x2): accumulators
// paired along q, b-operands come pre-paired from 16B shared loads.

#define NP 64
#define SP_S 68    // preds stride: 272B = 16 mod 128 -> float4 rows conflict-free
#define ST_S 65    // target staging stride (scalar transpose reads)
#define STT_S 68   // transposed targets: 16B-aligned float4/ulonglong2 rows

typedef unsigned long long u64;

__device__ __forceinline__ u64 pack2(float x) {
    u64 r; asm("mov.b64 %0, {%1, %1};" : "=l"(r) : "f"(x)); return r;
}
__device__ __forceinline__ void ffma2(u64& d, u64 a, u64 b) {
    asm("fma.rn.f32x2 %0, %1, %2, %0;" : "+l"(d) : "l"(a), "l"(b));
}
__device__ __forceinline__ void unpack2(float& lo, float& hi, u64 v) {
    asm("mov.b64 {%0, %1}, %2;" : "=f"(lo), "=f"(hi) : "l"(v));
}

__global__ __launch_bounds__(256, 4)
void cross_mse_loss_kernel(const float* __restrict__ inp,
                           const float* __restrict__ tgt,
                           float* __restrict__ out)
{
    __shared__ __align__(16) float sp[NP * SP_S];     // preds [p][d], d=63 padded 0
    __shared__ __align__(16) float st[NP * ST_S];     // staging [q][d]; aliased rm/cm
    __shared__ __align__(16) float st_t[NP * STT_S];  // targets transposed [d][q]
    __shared__ float conf[NP];
    __shared__ float cinv2[NP];
    __shared__ float pn[NP];
    __shared__ float qn[NP];
    __shared__ float pp[256];
    __shared__ float qp[256];
    __shared__ float red[128];

    float* rm = st;              // [16][65] row-min partials (by tx)
    float* cm = st + 16 * 65;    // [16][65] col-min partials (by ty)

    const int bs  = blockIdx.x;
    const int tid = threadIdx.x;

    const float* ip = inp + (size_t)bs * (NP * 64);
    const float* tp = tgt + (size_t)bs * 63 * 64;

    // ---- Load preds (+conf) via float4; zero-pad d=63 ----
    const float4* ip4 = (const float4*)ip;
    #pragma unroll
    for (int r = 0; r < 4; r++) {
        int idx = tid + r * 256;
        float4 v = ip4[idx];
        int p  = idx >> 4;
        int d4 = (idx & 15) << 2;
        float* row = sp + p * SP_S + d4;
        if (d4 == 60) {
            row[0] = v.x; row[1] = v.y; row[2] = v.z; row[3] = 0.0f;
            conf[p] = v.w;
            float ci = 1.0f / v.w;
            cinv2[p] = ci * ci;
        } else {
            row[0] = v.x; row[1] = v.y; row[2] = v.z; row[3] = v.w;
        }
    }
    // ---- Load targets (coalesced scalar); zero-pad d=63 ----
    #pragma unroll
    for (int r = 0; r < 16; r++) {
        int i = tid + r * 256;
        if (i < NP * 63) {
            int q = i / 63;
            int d = i - q * 63;
            st[q * ST_S + d] = tp[i];
        }
    }
    if (tid < NP) st[tid * ST_S + 63] = 0.0f;
    __syncthreads();

    // ---- Transpose targets into st_t[d][q] ----
    #pragma unroll
    for (int r = 0; r < 16; r++) {
        int i = tid + r * 256;
        int d = i >> 6;
        int q = i & 63;
        st_t[d * STT_S + q] = st[q * ST_S + d];
    }
    // ---- Norm partials (k rotated by p to kill sp-stride-68 conflicts) ----
    {
        int p = tid & 63;
        int g = tid >> 6;
        const float* ap = sp + p * SP_S + g * 16;
        const float* bp = st + p * ST_S + g * 16;
        float s1 = 0.0f, s2 = 0.0f;
        #pragma unroll
        for (int k = 0; k < 16; k++) {
            float a = ap[(k + p) & 15];
            float b = bp[k];
            s1 = fmaf(a, a, s1);
            s2 = fmaf(b, b, s2);
        }
        pp[tid] = s1;
        qp[tid] = s2;
    }
    __syncthreads();
    if (tid < NP) {
        pn[tid] = (pp[tid] + pp[tid + 64]) + (pp[tid + 128] + pp[tid + 192]);
    } else if (tid < 2 * NP) {
        int q = tid - NP;
        qn[q] = (qp[q] + qp[q + 64]) + (qp[q + 128] + qp[q + 192]);
    }
    __syncthreads();

    // ---- Main loop: 4x4 tile, f32x2-packed along q ----
    const int tx = tid & 15;
    const int ty = tid >> 4;
    const int p0 = ty * 4;
    const int q0 = tx * 4;

    u64 acc[4][2];
    #pragma unroll
    for (int i = 0; i < 4; i++) { acc[i][0] = 0ull; acc[i][1] = 0ull; }

    const char* bbase = (const char*)(st_t + q0);
    const char* abase = (const char*)(sp + p0 * SP_S);

    #pragma unroll 4
    for (int dc = 0; dc < 64; dc += 4) {
        ulonglong2 b0 = *(const ulonglong2*)(bbase + (size_t)(dc + 0) * (STT_S * 4));
        ulonglong2 b1 = *(const ulonglong2*)(bbase + (size_t)(dc + 1) * (STT_S * 4));
        ulonglong2 b2 = *(const ulonglong2*)(bbase + (size_t)(dc + 2) * (STT_S * 4));
        ulonglong2 b3 = *(const ulonglong2*)(bbase + (size_t)(dc + 3) * (STT_S * 4));
        #pragma unroll
        for (int i = 0; i < 4; i++) {
            float4 av = *(const float4*)(abase + (size_t)i * (SP_S * 4) + dc * 4);
            u64 a0 = pack2(av.x), a1 = pack2(av.y), a2 = pack2(av.z), a3 = pack2(av.w);
            ffma2(acc[i][0], a0, b0.x); ffma2(acc[i][1], a0, b0.y);
            ffma2(acc[i][0], a1, b1.x); ffma2(acc[i][1], a1, b1.y);
            ffma2(acc[i][0], a2, b2.x); ffma2(acc[i][1], a2, b2.y);
            ffma2(acc[i][0], a3, b3.x); ffma2(acc[i][1], a3, b3.y);
        }
    }

    // ---- Epilogue: d^2, partial row/col mins on squared distances ----
    float pnr[4], ci2[4], qnr[4];
    #pragma unroll
    for (int i = 0; i < 4; i++) { pnr[i] = pn[p0 + i]; ci2[i] = cinv2[p0 + i]; }
    #pragma unroll
    for (int j = 0; j < 4; j++) qnr[j] = qn[q0 + j];

    float rmin[4] = {1e30f, 1e30f, 1e30f, 1e30f};
    float cmin[4] = {1e30f, 1e30f, 1e30f, 1e30f};
    #pragma unroll
    for (int i = 0; i < 4; i++) {
        float d2v[4];
        unpack2(d2v[0], d2v[1], acc[i][0]);
        unpack2(d2v[2], d2v[3], acc[i][1]);
        #pragma unroll
        for (int j = 0; j < 4; j++) {
            float d2 = fmaxf(fmaf(-2.0f, d2v[j], pnr[i] + qnr[j]), 0.0f);
            rmin[i] = fminf(rmin[i], d2);
            cmin[j] = fminf(cmin[j], d2 * ci2[i]);
        }
    }
    __syncthreads();   // st staging dead; rm/cm reuse is safe after this
    #pragma unroll
    for (int i = 0; i < 4; i++) rm[tx * 65 + p0 + i] = rmin[i];
    #pragma unroll
    for (int j = 0; j < 4; j++) cm[ty * 65 + q0 + j] = cmin[j];
    __syncthreads();

    // ---- Final mins + 128 sqrts + block sum ----
    float val = 0.0f;
    if (tid < NP) {
        const int p = tid;
        float m = rm[p];
        #pragma unroll
        for (int t = 1; t < 16; t++) m = fminf(m, rm[t * 65 + p]);
        val = conf[p] * sqrtf(m);
    } else if (tid < 2 * NP) {
        const int q = tid - NP;
        float m = cm[q];
        #pragma unroll
        for (int t = 1; t < 16; t++) m = fminf(m, cm[t * 65 + q]);
        val = sqrtf(m);
    }

    if (tid < 128) red[tid] = val;
    __syncthreads();
    if (tid < 64) red[tid] += red[tid + 64];
    __syncthreads();
    if (tid < 32) {
        float s = red[tid] + red[tid + 32];
        #pragma unroll
        for (int off = 16; off > 0; off >>= 1)
            s += __shfl_down_sync(0xFFFFFFFFu, s, off);
        if (tid == 0) out[bs] = s;
    }
}

extern "C" void kernel_launch(void* const* d_in, const int* in_sizes, int n_in,
                              void* d_out, int out_size)
{
    const float* inp = (const float*)d_in[0];
    const float* tgt = (const float*)d_in[1];
    float* out = (float*)d_out;
    cross_mse_loss_kernel<<<1024, 256>>>(inp, tgt, out);
}